// round 7
// baseline (speedup 1.0000x reference)
#include <cuda_runtime.h>
#include <math.h>
#include <stdint.h>

#define T_TOK 16
#define NU    4096
#define E     128
#define H     128
#define LP    32
#define NP    1024
#define G4    512   // 4*H

// ---------------- scratch (static device memory; allocation-free) ----------------
__device__ __align__(16) float g_gpre_f[(size_t)T_TOK*NU*G4];   // gate-interleaved
__device__ __align__(16) float g_gpre_b[(size_t)T_TOK*NU*G4];
__device__ __align__(16) float g_hf[(size_t)T_TOK*NU*H];
__device__ __align__(16) float g_hb[(size_t)T_TOK*NU*H];
__device__ __align__(16) float g_cf[NU*H];
__device__ __align__(16) float g_cb[NU*H];
__device__ __align__(16) float g_hcat[(size_t)T_TOK*NU*2*H];
__device__ __align__(16) float g_outlin[(size_t)T_TOK*NU*E];
__device__ __align__(16) float g_tokfeat[NU*E];
__device__ int   g_toklen[NU];
__device__ int   g_rm_tb[T_TOK*NU];
__device__ int   g_rm_pf[LP*NP];
__device__ int   g_rm_pb[LP*NP];
__device__ int   g_plen[NP];
__device__ __align__(16) float g_gpre_pf[(size_t)LP*NP*G4];
__device__ __align__(16) float g_gpre_pb[(size_t)LP*NP*G4];
__device__ __align__(16) float g_hpf[(size_t)LP*NP*H];
__device__ __align__(16) float g_hpb[(size_t)LP*NP*H];
__device__ __align__(16) float g_cpf[NP*H];
__device__ __align__(16) float g_cpb[NP*H];
__device__ __align__(16) float g_hcatp[(size_t)LP*NP*2*H];
__device__ __align__(16) float g_zero[NU*H];   // zero-initialized, never written

__device__ __forceinline__ float sigm(float x) { return 1.f / (1.f + expf(-x)); }

// ---------------- tf32 mma.sync helpers (plain compute_103, no 'a' features) ----
__device__ __forceinline__ uint32_t f2tf(float f) {
    uint32_t r; asm("cvt.rna.tf32.f32 %0, %1;" : "=r"(r) : "f"(f)); return r;
}
__device__ __forceinline__ void mma8(float& d0, float& d1, float& d2, float& d3,
                                     uint32_t a0, uint32_t a1, uint32_t a2, uint32_t a3,
                                     uint32_t b0, uint32_t b1) {
    asm volatile(
        "mma.sync.aligned.m16n8k8.row.col.f32.tf32.tf32.f32 "
        "{%0,%1,%2,%3}, {%4,%5,%6,%7}, {%8,%9}, {%0,%1,%2,%3};"
        : "+f"(d0), "+f"(d1), "+f"(d2), "+f"(d3)
        : "r"(a0), "r"(a1), "r"(a2), "r"(a3), "r"(b0), "r"(b1));
}
// gate interleave: output col j <- original weight row (j&3)*128 + (j>>2)
__device__ __forceinline__ int gperm(int j) { return (j & 3) * 128 + (j >> 2); }

// ---------------- prep: token lengths + backward-input row map ----------------
__global__ void prep_tok(const int* __restrict__ units, int* __restrict__ toklen,
                         int* __restrict__ rm_b) {
    int n = blockIdx.x * blockDim.x + threadIdx.x;
    if (n >= NU) return;
    int len = T_TOK;
    for (int t = 0; t < T_TOK; t++)
        if (units[t*NU + n] == 0) { len = t; break; }
    toklen[n] = len;
    for (int s = 0; s < T_TOK; s++) {
        int st = len - 1 - s;
        st = st < 0 ? 0 : (st > T_TOK-1 ? T_TOK-1 : st);
        rm_b[s*NU + n] = units[st*NU + n];
    }
}

// ---------------- prep: path lengths + gather row maps ----------------
__global__ void prep_path(const int* __restrict__ paths, const int* __restrict__ upd,
                          const int* __restrict__ ppd, int* __restrict__ plen_out,
                          int* __restrict__ rm_f, int* __restrict__ rm_b) {
    int p = blockIdx.x * blockDim.x + threadIdx.x;
    if (p >= NP) return;
    int d = 0, cum = 0;
    for (int i = 0; i < 8; i++) { int c = ppd[i]; if (p < cum + c) { d = i; break; } cum += c; }
    int off = 0;
    for (int i = 0; i < d; i++) off += upd[i];
    int un = upd[d];
    int fe = LP;
    for (int l = 0; l < LP; l++)
        if (paths[l*NP + p] == -1) { fe = l; break; }
    int plen = LP;
    for (int l = 0; l < LP; l++) {
        int pv = paths[l*NP + p];
        bool m = (l < fe) ? (pv < 0 || pv > un) : true;
        if (m) { plen = l; break; }
    }
    plen_out[p] = plen;
    for (int l = 0; l < LP; l++) {
        int pv = paths[l*NP + p];
        bool keep = (l < fe) && pv >= 0 && pv < un;
        int pvc = pv < 0 ? 0 : pv;
        int gidx = pvc + off; if (gidx > NU-1) gidx = NU-1;
        rm_f[l*NP + p] = keep ? gidx : -1;
    }
    for (int s = 0; s < LP; s++) {
        int sl = plen - 1 - s;
        sl = sl < 0 ? 0 : (sl > LP-1 ? LP-1 : sl);
        int pv = paths[sl*NP + p];
        bool keep = (sl < fe) && pv >= 0 && pv < un;
        int pvc = pv < 0 ? 0 : pv;
        int gidx = pvc + off; if (gidx > NU-1) gidx = NU-1;
        rm_b[s*NP + p] = keep ? gidx : -1;
    }
}

// ---------------- clear LSTM cell state ----------------
__global__ void clear_c() {
    int i = blockIdx.x * 256 + threadIdx.x;
    if (i < NU*H) { g_cf[i] = 0.f; g_cb[i] = 0.f; }
    if (i < NP*H) { g_cpf[i] = 0.f; g_cpb[i] = 0.f; }
}

// ===================== tf32 mma.sync GEMM =====================
// C[m][j] = bias[pj] + sum_k Arow(m)[k] * B[pj][k],  pj = permB ? gperm(j) : j
// Arow(m) = rowmap ? (rowmap[m]>=0 ? A+rowmap[m]*K : 0) : A+m*K
// grid (N/128, M/128); 256 threads; warp tile 64x32 (2x4 warps); K multiple of 32.
__global__ __launch_bounds__(256) void mma_gemm(
    const float* __restrict__ A, const int* __restrict__ rowmap,
    const float* __restrict__ B, const float* __restrict__ bias,
    float* __restrict__ C, int M, int N, int K, int permB)
{
    __shared__ uint32_t As[128][36];
    __shared__ uint32_t Bs[128][36];
    __shared__ int rid[128];
    int tid = threadIdx.x, lane = tid & 31, wid = tid >> 5;
    int wm = (wid >> 2) * 64, wn = (wid & 3) * 32;
    int m0 = blockIdx.y * 128, n0 = blockIdx.x * 128;
    if (tid < 128) rid[tid] = rowmap ? rowmap[m0 + tid] : (m0 + tid);
    float acc[4][4][4];
#pragma unroll
    for (int a = 0; a < 4; a++)
#pragma unroll
        for (int b = 0; b < 4; b++)
#pragma unroll
            for (int q = 0; q < 4; q++) acc[a][b][q] = 0.f;
    __syncthreads();

    for (int kc = 0; kc < K; kc += 32) {
        for (int i = tid; i < 1024; i += 256) {          // 128 rows x 8 float4
            int r = i >> 3, q = i & 7;
            int src = rid[r];
            float4 v = make_float4(0.f, 0.f, 0.f, 0.f);
            if (src >= 0) v = *(const float4*)(A + (size_t)src * K + kc + q * 4);
            As[r][q*4+0] = f2tf(v.x); As[r][q*4+1] = f2tf(v.y);
            As[r][q*4+2] = f2tf(v.z); As[r][q*4+3] = f2tf(v.w);
        }
        for (int i = tid; i < 1024; i += 256) {
            int r = i >> 3, q = i & 7;
            int srcr = permB ? gperm(n0 + r) : (n0 + r);
            float4 v = *(const float4*)(B + (size_t)srcr * K + kc + q * 4);
            Bs[r][q*4+0] = f2tf(v.x); Bs[r][q*4+1] = f2tf(v.y);
            Bs[r][q*4+2] = f2tf(v.z); Bs[r][q*4+3] = f2tf(v.w);
        }
        __syncthreads();
#pragma unroll
        for (int ks = 0; ks < 4; ks++) {
            int k8 = ks * 8, kc4 = k8 + (lane & 3);
            uint32_t af[4][4];
#pragma unroll
            for (int ma = 0; ma < 4; ma++) {
                int r = wm + ma * 16 + (lane >> 2);
                af[ma][0] = As[r    ][kc4];
                af[ma][1] = As[r + 8][kc4];
                af[ma][2] = As[r    ][kc4 + 4];
                af[ma][3] = As[r + 8][kc4 + 4];
            }
#pragma unroll
            for (int nb = 0; nb < 4; nb++) {
                int cn = wn + nb * 8 + (lane >> 2);
                uint32_t b0 = Bs[cn][kc4];
                uint32_t b1 = Bs[cn][kc4 + 4];
#pragma unroll
                for (int ma = 0; ma < 4; ma++)
                    mma8(acc[ma][nb][0], acc[ma][nb][1], acc[ma][nb][2], acc[ma][nb][3],
                         af[ma][0], af[ma][1], af[ma][2], af[ma][3], b0, b1);
            }
        }
        __syncthreads();
    }
#pragma unroll
    for (int ma = 0; ma < 4; ma++) {
        int m = m0 + wm + ma * 16 + (lane >> 2);
#pragma unroll
        for (int nb = 0; nb < 4; nb++) {
            int j = n0 + wn + nb * 8 + (lane & 3) * 2;
            float b0v = bias[permB ? gperm(j)     : j];
            float b1v = bias[permB ? gperm(j + 1) : j + 1];
            *(float2*)(C + (size_t)m * N + j) =
                make_float2(acc[ma][nb][0] + b0v, acc[ma][nb][1] + b1v);
            *(float2*)(C + (size_t)(m + 8) * N + j) =
                make_float2(acc[ma][nb][2] + b0v, acc[ma][nb][3] + b1v);
        }
    }
}

// ===================== fused LSTM step (tf32 mma + cell update) =====================
// gates[m][j] = gpre[m][j] + sum_k h_prev[m][k] * Wh[gperm(j)][k]  (j gate-interleaved)
// then c/h update. grid (batch/128, 4, 2); z selects direction.
struct LArgs {
    const float* gpre;    // [batch*512] interleaved, this step
    const float* h_prev;  // [batch*128]
    float*       h_out;   // [batch*128]
    float*       c;       // [batch*128]
    const float* Wh;      // [512*128] original gate-major rows
};

__global__ __launch_bounds__(256) void lstm_mma(LArgs F, LArgs Bd) {
    LArgs a = blockIdx.z ? Bd : F;
    __shared__ uint32_t As[128][36];
    __shared__ uint32_t Bs[128][36];
    int tid = threadIdx.x, lane = tid & 31, wid = tid >> 5;
    int wm = (wid >> 2) * 64, wn = (wid & 3) * 32;
    int m0 = blockIdx.x * 128, n0 = blockIdx.y * 128;
    float acc[4][4][4];
#pragma unroll
    for (int x = 0; x < 4; x++)
#pragma unroll
        for (int y = 0; y < 4; y++)
#pragma unroll
            for (int q = 0; q < 4; q++) acc[x][y][q] = 0.f;

    for (int kc = 0; kc < 128; kc += 32) {
        for (int i = tid; i < 1024; i += 256) {
            int r = i >> 3, q = i & 7;
            float4 v = *(const float4*)(a.h_prev + (size_t)(m0 + r) * 128 + kc + q * 4);
            As[r][q*4+0] = f2tf(v.x); As[r][q*4+1] = f2tf(v.y);
            As[r][q*4+2] = f2tf(v.z); As[r][q*4+3] = f2tf(v.w);
        }
        for (int i = tid; i < 1024; i += 256) {
            int r = i >> 3, q = i & 7;
            float4 v = *(const float4*)(a.Wh + (size_t)gperm(n0 + r) * 128 + kc + q * 4);
            Bs[r][q*4+0] = f2tf(v.x); Bs[r][q*4+1] = f2tf(v.y);
            Bs[r][q*4+2] = f2tf(v.z); Bs[r][q*4+3] = f2tf(v.w);
        }
        __syncthreads();
#pragma unroll
        for (int ks = 0; ks < 4; ks++) {
            int k8 = ks * 8, kc4 = k8 + (lane & 3);
            uint32_t af[4][4];
#pragma unroll
            for (int ma = 0; ma < 4; ma++) {
                int r = wm + ma * 16 + (lane >> 2);
                af[ma][0] = As[r    ][kc4];
                af[ma][1] = As[r + 8][kc4];
                af[ma][2] = As[r    ][kc4 + 4];
                af[ma][3] = As[r + 8][kc4 + 4];
            }
#pragma unroll
            for (int nb = 0; nb < 4; nb++) {
                int cn = wn + nb * 8 + (lane >> 2);
                uint32_t b0 = Bs[cn][kc4];
                uint32_t b1 = Bs[cn][kc4 + 4];
#pragma unroll
                for (int ma = 0; ma < 4; ma++)
                    mma8(acc[ma][nb][0], acc[ma][nb][1], acc[ma][nb][2], acc[ma][nb][3],
                         af[ma][0], af[ma][1], af[ma][2], af[ma][3], b0, b1);
            }
        }
        __syncthreads();
    }
    // epilogue: + gpre, pairwise gate exchange, LSTM cell update
#pragma unroll
    for (int ma = 0; ma < 4; ma++) {
        int m = m0 + wm + ma * 16 + (lane >> 2);
#pragma unroll
        for (int nb = 0; nb < 4; nb++) {
            int j = n0 + wn + nb * 8 + (lane & 3) * 2;
#pragma unroll
            for (int hh = 0; hh < 2; hh++) {
                int mh = m + hh * 8;
                float g0 = acc[ma][nb][hh*2]     + a.gpre[(size_t)mh * 512 + j];
                float g1 = acc[ma][nb][hh*2 + 1] + a.gpre[(size_t)mh * 512 + j + 1];
                float p0 = __shfl_xor_sync(0xffffffffu, g0, 1);
                float p1 = __shfl_xor_sync(0xffffffffu, g1, 1);
                if (!(lane & 1)) {
                    // even lane: g0=i, g1=f ; partner: p0=g, p1=o
                    int cell = j >> 2;
                    size_t ix = (size_t)mh * 128 + cell;
                    float cn = sigm(g1) * a.c[ix] + sigm(g0) * tanhf(p0);
                    float hn = sigm(p1) * tanhf(cn);
                    a.c[ix] = cn;
                    a.h_out[ix] = hn;
                }
            }
        }
    }
}

// ---------------- concat fwd/bwd hidden states ----------------
__global__ void hcat_tok(const float* __restrict__ hf, const float* __restrict__ hb,
                         const int* __restrict__ toklen, float* __restrict__ hcat) {
    size_t idx = (size_t)blockIdx.x * 256 + threadIdx.x;
    int k = (int)(idx & 127);
    size_t row = idx >> 7;
    int n = (int)(row & (NU-1));
    int t = (int)(row >> 12);
    int len = toklen[n];
    bool valid = t < len;
    int rev = len - 1 - t;
    rev = rev < 0 ? 0 : (rev > T_TOK-1 ? T_TOK-1 : rev);
    float vf = valid ? hf[idx] : 0.f;
    float vb = valid ? hb[((size_t)(rev*NU + n))*128 + k] : 0.f;
    hcat[row*256 + k]       = vf;
    hcat[row*256 + 128 + k] = vb;
}

__global__ void hcat_path(const float* __restrict__ hpf, const float* __restrict__ hpb,
                          const int* __restrict__ plen, float* __restrict__ hcatp) {
    size_t idx = (size_t)blockIdx.x * 256 + threadIdx.x;
    int k = (int)(idx & 127);
    size_t row = idx >> 7;
    int p = (int)(row & (NP-1));
    int l = (int)(row >> 10);
    int pl = plen[p];
    bool valid = l < pl;
    int rev = pl - 1 - l;
    rev = rev < 0 ? 0 : (rev > LP-1 ? LP-1 : rev);
    float vf = valid ? hpf[idx] : 0.f;
    float vb = valid ? hpb[((size_t)(rev*NP + p))*128 + k] : 0.f;
    hcatp[row*256 + k]       = vf;
    hcatp[row*256 + 128 + k] = vb;
}

// ---------------- attention ----------------
__device__ __forceinline__ float blk_sum128(float v, float* r4) {
#pragma unroll
    for (int o = 16; o > 0; o >>= 1) v += __shfl_xor_sync(0xffffffffu, v, o);
    __syncthreads();
    if ((threadIdx.x & 31) == 0) r4[threadIdx.x >> 5] = v;
    __syncthreads();
    return r4[0] + r4[1] + r4[2] + r4[3];
}

__global__ void attn_kernel(const float* __restrict__ outlin, const int* __restrict__ toklen,
                            const float* __restrict__ ln_g, const float* __restrict__ ln_b,
                            const float* __restrict__ attn_w, const float* __restrict__ attn_b,
                            float* __restrict__ tokfeat) {
    int n = blockIdx.x, e = threadIdx.x;
    __shared__ float r4[4];
    __shared__ float sc[T_TOK];
    int len = toklen[n];
    float g = ln_g[e], bb = ln_b[e], aw = attn_w[e], ab = attn_b[0];
    float xv[T_TOK];
    for (int t = 0; t < T_TOK; t++) {
        float x = outlin[((size_t)(t*NU + n))*128 + e];
        xv[t] = x;
        float m = blk_sum128(x, r4) * (1.f/128.f);
        float d = x - m;
        float v = blk_sum128(d*d, r4) * (1.f/128.f);
        float q = tanhf(d * rsqrtf(v + 1e-5f) * g + bb);
        float s = blk_sum128(q * aw, r4);
        if (e == 0) sc[t] = (t < len) ? (s + ab) : -1e9f;
    }
    __syncthreads();
    float mx = -3.4e38f;
#pragma unroll
    for (int t = 0; t < T_TOK; t++) mx = fmaxf(mx, sc[t]);
    float ww[T_TOK]; float den = 0.f;
#pragma unroll
    for (int t = 0; t < T_TOK; t++) { ww[t] = expf(sc[t] - mx); den += ww[t]; }
    float inv = 1.f / den;
    float acc = 0.f;
#pragma unroll
    for (int t = 0; t < T_TOK; t++) acc += ww[t] * inv * xv[t];
    tokfeat[(size_t)n*128 + e] = acc;
}

// ---------------- host ----------------
extern "C" void kernel_launch(void* const* d_in, const int* in_sizes, int n_in,
                              void* d_out, int out_size) {
    const int*   units   = (const int*)d_in[0];
    const int*   paths   = (const int*)d_in[1];
    const int*   upd     = (const int*)d_in[2];
    const int*   ppd     = (const int*)d_in[3];
    const float* emb     = (const float*)d_in[4];
    const float* tl_Wif  = (const float*)d_in[5];
    const float* tl_Whf  = (const float*)d_in[6];
    const float* tl_bf   = (const float*)d_in[7];
    const float* tl_Wib  = (const float*)d_in[8];
    const float* tl_Whb  = (const float*)d_in[9];
    const float* tl_bb   = (const float*)d_in[10];
    const float* lin_W   = (const float*)d_in[11];
    const float* lin_b   = (const float*)d_in[12];
    const float* ln_g    = (const float*)d_in[13];
    const float* ln_bb   = (const float*)d_in[14];
    const float* attn_w  = (const float*)d_in[15];
    const float* attn_b  = (const float*)d_in[16];
    const float* pl_Wif  = (const float*)d_in[17];
    const float* pl_Whf  = (const float*)d_in[18];
    const float* pl_bf   = (const float*)d_in[19];
    const float* pl_Wib  = (const float*)d_in[20];
    const float* pl_Whb  = (const float*)d_in[21];
    const float* pl_bb   = (const float*)d_in[22];
    const float* ul_W    = (const float*)d_in[23];
    const float* ul_b    = (const float*)d_in[24];
    float* out = (float*)d_out;

    float *gpre_f, *gpre_b, *hf, *hb, *cf, *cb, *hcat, *outlin, *tokfeat;
    float *gpre_pf, *gpre_pb, *hpf, *hpb, *cpf, *cpb, *hcatp, *zero;
    int *toklen, *rm_tb, *rm_pf, *rm_pb, *plen;
    cudaGetSymbolAddress((void**)&gpre_f,  g_gpre_f);
    cudaGetSymbolAddress((void**)&gpre_b,  g_gpre_b);
    cudaGetSymbolAddress((void**)&hf,      g_hf);
    cudaGetSymbolAddress((void**)&hb,      g_hb);
    cudaGetSymbolAddress((void**)&cf,      g_cf);
    cudaGetSymbolAddress((void**)&cb,      g_cb);
    cudaGetSymbolAddress((void**)&hcat,    g_hcat);
    cudaGetSymbolAddress((void**)&outlin,  g_outlin);
    cudaGetSymbolAddress((void**)&tokfeat, g_tokfeat);
    cudaGetSymbolAddress((void**)&gpre_pf, g_gpre_pf);
    cudaGetSymbolAddress((void**)&gpre_pb, g_gpre_pb);
    cudaGetSymbolAddress((void**)&hpf,     g_hpf);
    cudaGetSymbolAddress((void**)&hpb,     g_hpb);
    cudaGetSymbolAddress((void**)&cpf,     g_cpf);
    cudaGetSymbolAddress((void**)&cpb,     g_cpb);
    cudaGetSymbolAddress((void**)&hcatp,   g_hcatp);
    cudaGetSymbolAddress((void**)&zero,    g_zero);
    cudaGetSymbolAddress((void**)&toklen,  g_toklen);
    cudaGetSymbolAddress((void**)&rm_tb,   g_rm_tb);
    cudaGetSymbolAddress((void**)&rm_pf,   g_rm_pf);
    cudaGetSymbolAddress((void**)&rm_pb,   g_rm_pb);
    cudaGetSymbolAddress((void**)&plen,    g_plen);

    prep_tok<<<(NU+255)/256, 256>>>(units, toklen, rm_tb);
    clear_c<<<(NU*H+255)/256, 256>>>();

    // token input-gate GEMMs (tf32 mma, gate-interleaved output)
    mma_gemm<<<dim3(4, T_TOK*NU/128), 256>>>(emb, units, tl_Wif, tl_bf, gpre_f, T_TOK*NU, G4, E, 1);
    mma_gemm<<<dim3(4, T_TOK*NU/128), 256>>>(emb, rm_tb, tl_Wib, tl_bb, gpre_b, T_TOK*NU, G4, E, 1);

    // token recurrent steps (fused tf32 mma + cell update; fwd+bwd via grid.z)
    for (int t = 0; t < T_TOK; t++) {
        LArgs af { gpre_f + (size_t)t*NU*G4, t ? hf + (size_t)(t-1)*NU*H : zero,
                   hf + (size_t)t*NU*H, cf, tl_Whf };
        LArgs ab { gpre_b + (size_t)t*NU*G4, t ? hb + (size_t)(t-1)*NU*H : zero,
                   hb + (size_t)t*NU*H, cb, tl_Whb };
        lstm_mma<<<dim3(NU/128, 4, 2), 256>>>(af, ab);
    }

    hcat_tok<<<(int)((size_t)T_TOK*NU*H/256), 256>>>(hf, hb, toklen, hcat);
    mma_gemm<<<dim3(1, T_TOK*NU/128), 256>>>(hcat, nullptr, lin_W, lin_b, outlin, T_TOK*NU, E, 2*H, 0);
    attn_kernel<<<NU, 128>>>(outlin, toklen, ln_g, ln_bb, attn_w, attn_b, tokfeat);

    // path side
    prep_path<<<(NP+255)/256, 256>>>(paths, upd, ppd, plen, rm_pf, rm_pb);
    mma_gemm<<<dim3(4, LP*NP/128), 256>>>(tokfeat, rm_pf, pl_Wif, pl_bf, gpre_pf, LP*NP, G4, E, 1);
    mma_gemm<<<dim3(4, LP*NP/128), 256>>>(tokfeat, rm_pb, pl_Wib, pl_bb, gpre_pb, LP*NP, G4, E, 1);

    for (int s = 0; s < LP; s++) {
        LArgs af { gpre_pf + (size_t)s*NP*G4, s ? hpf + (size_t)(s-1)*NP*H : zero,
                   hpf + (size_t)s*NP*H, cpf, pl_Whf };
        LArgs ab { gpre_pb + (size_t)s*NP*G4, s ? hpb + (size_t)(s-1)*NP*H : zero,
                   hpb + (size_t)s*NP*H, cpb, pl_Whb };
        lstm_mma<<<dim3(NP/128, 4, 2), 256>>>(af, ab);
    }

    hcat_path<<<(int)((size_t)LP*NP*H/256), 256>>>(hpf, hpb, plen, hcatp);
    mma_gemm<<<dim3(1, LP*NP/128), 256>>>(hcatp, nullptr, ul_W, ul_b, out, LP*NP, E, 2*H, 0);
}

// round 9
// speedup vs baseline: 1.2086x; 1.2086x over previous
#include <cuda_runtime.h>
#include <math.h>
#include <stdint.h>

#define T_TOK 16
#define NU    4096
#define E     128
#define H     128
#define LP    32
#define NP    1024
#define G4    512   // 4*H

// ---------------- scratch (static device memory; allocation-free) ----------------
__device__ __align__(16) float g_gpre_f[(size_t)T_TOK*NU*G4];   // gate-interleaved
__device__ __align__(16) float g_gpre_b[(size_t)T_TOK*NU*G4];
__device__ __align__(16) float g_hf[(size_t)T_TOK*NU*H];
__device__ __align__(16) float g_hb[(size_t)T_TOK*NU*H];
__device__ __align__(16) float g_hcat[(size_t)T_TOK*NU*2*H];
__device__ __align__(16) float g_outlin[(size_t)T_TOK*NU*E];
__device__ __align__(16) float g_tokfeat[NU*E];
__device__ int   g_toklen[NU];
__device__ int   g_rm_tb[T_TOK*NU];
__device__ int   g_rm_pf[LP*NP];
__device__ int   g_rm_pb[LP*NP];
__device__ int   g_plen[NP];
__device__ __align__(16) float g_gpre_pf[(size_t)LP*NP*G4];
__device__ __align__(16) float g_gpre_pb[(size_t)LP*NP*G4];
__device__ __align__(16) float g_hpf[(size_t)LP*NP*H];
__device__ __align__(16) float g_hpb[(size_t)LP*NP*H];
__device__ __align__(16) float g_hcatp[(size_t)LP*NP*2*H];

// software grid barrier state (self-resetting; monotone generation)
__device__ unsigned g_bcnt = 0;
__device__ unsigned g_bgen = 0;

__device__ __forceinline__ float sigm(float x) { return 1.f / (1.f + expf(-x)); }

// ---------------- tf32 mma.sync helpers (plain compute_103, no 'a' features) ----
__device__ __forceinline__ uint32_t f2tf(float f) {
    uint32_t r; asm("cvt.rna.tf32.f32 %0, %1;" : "=r"(r) : "f"(f)); return r;
}
__device__ __forceinline__ void mma8(float& d0, float& d1, float& d2, float& d3,
                                     uint32_t a0, uint32_t a1, uint32_t a2, uint32_t a3,
                                     uint32_t b0, uint32_t b1) {
    asm volatile(
        "mma.sync.aligned.m16n8k8.row.col.f32.tf32.tf32.f32 "
        "{%0,%1,%2,%3}, {%4,%5,%6,%7}, {%8,%9}, {%0,%1,%2,%3};"
        : "+f"(d0), "+f"(d1), "+f"(d2), "+f"(d3)
        : "r"(a0), "r"(a1), "r"(a2), "r"(a3), "r"(b0), "r"(b1));
}
// gate interleave: output col j <- original weight row (j&3)*128 + (j>>2)
__device__ __forceinline__ int gperm(int j) { return (j & 3) * 128 + (j >> 2); }

__device__ __forceinline__ void grid_sync_() {
    __syncthreads();
    if (threadIdx.x == 0) {
        __threadfence();
        unsigned gen = *((volatile unsigned*)&g_bgen);
        unsigned n = gridDim.x;
        if (atomicAdd(&g_bcnt, 1) == n - 1) {
            *((volatile unsigned*)&g_bcnt) = 0;
            __threadfence();
            atomicExch(&g_bgen, gen + 1);
        } else {
            while (*((volatile unsigned*)&g_bgen) == gen) { }
        }
        __threadfence();
    }
    __syncthreads();
}

// ---------------- prep: token lengths + backward-input row map ----------------
__global__ void prep_tok(const int* __restrict__ units, int* __restrict__ toklen,
                         int* __restrict__ rm_b) {
    int n = blockIdx.x * blockDim.x + threadIdx.x;
    if (n >= NU) return;
    int len = T_TOK;
    for (int t = 0; t < T_TOK; t++)
        if (units[t*NU + n] == 0) { len = t; break; }
    toklen[n] = len;
    for (int s = 0; s < T_TOK; s++) {
        int st = len - 1 - s;
        st = st < 0 ? 0 : (st > T_TOK-1 ? T_TOK-1 : st);
        rm_b[s*NU + n] = units[st*NU + n];
    }
}

// ---------------- prep: path lengths + gather row maps ----------------
__global__ void prep_path(const int* __restrict__ paths, const int* __restrict__ upd,
                          const int* __restrict__ ppd, int* __restrict__ plen_out,
                          int* __restrict__ rm_f, int* __restrict__ rm_b) {
    int p = blockIdx.x * blockDim.x + threadIdx.x;
    if (p >= NP) return;
    int d = 0, cum = 0;
    for (int i = 0; i < 8; i++) { int c = ppd[i]; if (p < cum + c) { d = i; break; } cum += c; }
    int off = 0;
    for (int i = 0; i < d; i++) off += upd[i];
    int un = upd[d];
    int fe = LP;
    for (int l = 0; l < LP; l++)
        if (paths[l*NP + p] == -1) { fe = l; break; }
    int plen = LP;
    for (int l = 0; l < LP; l++) {
        int pv = paths[l*NP + p];
        bool m = (l < fe) ? (pv < 0 || pv > un) : true;
        if (m) { plen = l; break; }
    }
    plen_out[p] = plen;
    for (int l = 0; l < LP; l++) {
        int pv = paths[l*NP + p];
        bool keep = (l < fe) && pv >= 0 && pv < un;
        int pvc = pv < 0 ? 0 : pv;
        int gidx = pvc + off; if (gidx > NU-1) gidx = NU-1;
        rm_f[l*NP + p] = keep ? gidx : -1;
    }
    for (int s = 0; s < LP; s++) {
        int sl = plen - 1 - s;
        sl = sl < 0 ? 0 : (sl > LP-1 ? LP-1 : sl);
        int pv = paths[sl*NP + p];
        bool keep = (sl < fe) && pv >= 0 && pv < un;
        int pvc = pv < 0 ? 0 : pv;
        int gidx = pvc + off; if (gidx > NU-1) gidx = NU-1;
        rm_b[s*NP + p] = keep ? gidx : -1;
    }
}

// ===================== tf32 mma.sync GEMM =====================
// C[m][j] = bias[pj] + sum_k Arow(m)[k] * B[pj][k],  pj = permB ? gperm(j) : j
__global__ __launch_bounds__(256) void mma_gemm(
    const float* __restrict__ A, const int* __restrict__ rowmap,
    const float* __restrict__ B, const float* __restrict__ bias,
    float* __restrict__ C, int M, int N, int K, int permB)
{
    __shared__ uint32_t As[128][36];
    __shared__ uint32_t Bs[128][36];
    __shared__ int rid[128];
    int tid = threadIdx.x, lane = tid & 31, wid = tid >> 5;
    int wm = (wid >> 2) * 64, wn = (wid & 3) * 32;
    int m0 = blockIdx.y * 128, n0 = blockIdx.x * 128;
    if (tid < 128) rid[tid] = rowmap ? rowmap[m0 + tid] : (m0 + tid);
    float acc[4][4][4];
#pragma unroll
    for (int a = 0; a < 4; a++)
#pragma unroll
        for (int b = 0; b < 4; b++)
#pragma unroll
            for (int q = 0; q < 4; q++) acc[a][b][q] = 0.f;
    __syncthreads();

    for (int kc = 0; kc < K; kc += 32) {
        for (int i = tid; i < 1024; i += 256) {
            int r = i >> 3, q = i & 7;
            int src = rid[r];
            float4 v = make_float4(0.f, 0.f, 0.f, 0.f);
            if (src >= 0) v = *(const float4*)(A + (size_t)src * K + kc + q * 4);
            As[r][q*4+0] = f2tf(v.x); As[r][q*4+1] = f2tf(v.y);
            As[r][q*4+2] = f2tf(v.z); As[r][q*4+3] = f2tf(v.w);
        }
        for (int i = tid; i < 1024; i += 256) {
            int r = i >> 3, q = i & 7;
            int srcr = permB ? gperm(n0 + r) : (n0 + r);
            float4 v = *(const float4*)(B + (size_t)srcr * K + kc + q * 4);
            Bs[r][q*4+0] = f2tf(v.x); Bs[r][q*4+1] = f2tf(v.y);
            Bs[r][q*4+2] = f2tf(v.z); Bs[r][q*4+3] = f2tf(v.w);
        }
        __syncthreads();
#pragma unroll
        for (int ks = 0; ks < 4; ks++) {
            int kc4 = ks * 8 + (lane & 3);
            uint32_t af[4][4];
#pragma unroll
            for (int ma = 0; ma < 4; ma++) {
                int r = wm + ma * 16 + (lane >> 2);
                af[ma][0] = As[r    ][kc4];
                af[ma][1] = As[r + 8][kc4];
                af[ma][2] = As[r    ][kc4 + 4];
                af[ma][3] = As[r + 8][kc4 + 4];
            }
#pragma unroll
            for (int nb = 0; nb < 4; nb++) {
                int cn = wn + nb * 8 + (lane >> 2);
                uint32_t b0 = Bs[cn][kc4];
                uint32_t b1 = Bs[cn][kc4 + 4];
#pragma unroll
                for (int ma = 0; ma < 4; ma++)
                    mma8(acc[ma][nb][0], acc[ma][nb][1], acc[ma][nb][2], acc[ma][nb][3],
                         af[ma][0], af[ma][1], af[ma][2], af[ma][3], b0, b1);
            }
        }
        __syncthreads();
    }
#pragma unroll
    for (int ma = 0; ma < 4; ma++) {
        int m = m0 + wm + ma * 16 + (lane >> 2);
#pragma unroll
        for (int nb = 0; nb < 4; nb++) {
            int j = n0 + wn + nb * 8 + (lane & 3) * 2;
            float b0v = bias[permB ? gperm(j)     : j];
            float b1v = bias[permB ? gperm(j + 1) : j + 1];
            *(float2*)(C + (size_t)m * N + j) =
                make_float2(acc[ma][nb][0] + b0v, acc[ma][nb][1] + b1v);
            *(float2*)(C + (size_t)(m + 8) * N + j) =
                make_float2(acc[ma][nb][2] + b0v, acc[ma][nb][3] + b1v);
        }
    }
}

// ===================== persistent BiLSTM recurrence =====================
// One launch runs all T steps. CTA owns (dir, m-slice of 128, gate quadrant of 128).
// Wh quadrant resident in SMEM (tf32); c resident in SMEM; steps separated by a
// software grid barrier. gates[m][j] = gpre[t][m][j] + h[t-1][m] . Wh[gperm(j)]
#define SM_WS 0
#define SM_AS 67584                       // Ws: 128 x 132 u32
#define SM_CS (67584 + 18432)             // As: 128 x 36 u32
#define PERSIST_SMEM (67584 + 18432 + 16896)   // c:  128 x 33 f32

__global__ __launch_bounds__(256, 2) void lstm_persist(
    const float* __restrict__ gpre_f, const float* __restrict__ gpre_b,
    float* __restrict__ hf_, float* __restrict__ hb_,
    const float* __restrict__ Whf, const float* __restrict__ Whb,
    int batch, int T)
{
    extern __shared__ char smch[];
    uint32_t (*Ws)[132] = (uint32_t (*)[132])(smch + SM_WS);
    uint32_t (*As)[36]  = (uint32_t (*)[36])(smch + SM_AS);
    float* c_s = (float*)(smch + SM_CS);

    int mblocks = batch >> 7;
    int bid = blockIdx.x;
    int dir = bid / (mblocks * 4);
    int rem = bid % (mblocks * 4);
    int mq = rem >> 2, nq = rem & 3;
    const float* gpre = dir ? gpre_b : gpre_f;
    float*       hout = dir ? hb_    : hf_;
    const float* Wh   = dir ? Whb    : Whf;

    int tid = threadIdx.x, lane = tid & 31, wid = tid >> 5;
    int wm = (wid >> 2) * 64, wn = (wid & 3) * 32;
    int m0 = mq * 128;

    // load this quadrant's Wh (gate-interleaved rows) once, f32->tf32
    for (int i = tid; i < 4096; i += 256) {
        int r = i >> 5, q = i & 31;
        float4 v = *(const float4*)(Wh + (size_t)gperm(nq * 128 + r) * 128 + q * 4);
        Ws[r][q*4+0] = f2tf(v.x); Ws[r][q*4+1] = f2tf(v.y);
        Ws[r][q*4+2] = f2tf(v.z); Ws[r][q*4+3] = f2tf(v.w);
    }
    for (int i = tid; i < 128 * 33; i += 256) c_s[i] = 0.f;
    __syncthreads();

    for (int t = 0; t < T; t++) {
        float acc[4][4][4];
#pragma unroll
        for (int x = 0; x < 4; x++)
#pragma unroll
            for (int y = 0; y < 4; y++)
#pragma unroll
                for (int q = 0; q < 4; q++) acc[x][y][q] = 0.f;

        if (t > 0) {
            const float* hprev = hout + (size_t)(t - 1) * batch * 128;
            for (int kc = 0; kc < 128; kc += 32) {
                for (int i = tid; i < 1024; i += 256) {
                    int r = i >> 3, q = i & 7;
                    float4 v = *(const float4*)(hprev + (size_t)(m0 + r) * 128 + kc + q * 4);
                    As[r][q*4+0] = f2tf(v.x); As[r][q*4+1] = f2tf(v.y);
                    As[r][q*4+2] = f2tf(v.z); As[r][q*4+3] = f2tf(v.w);
                }
                __syncthreads();
#pragma unroll
                for (int ks = 0; ks < 4; ks++) {
                    int ka = ks * 8 + (lane & 3);        // col within As chunk
                    int kb = kc + ka;                    // col within resident Ws
                    uint32_t af[4][4];
#pragma unroll
                    for (int ma = 0; ma < 4; ma++) {
                        int r = wm + ma * 16 + (lane >> 2);
                        af[ma][0] = As[r    ][ka];
                        af[ma][1] = As[r + 8][ka];
                        af[ma][2] = As[r    ][ka + 4];
                        af[ma][3] = As[r + 8][ka + 4];
                    }
#pragma unroll
                    for (int nb = 0; nb < 4; nb++) {
                        int cn = wn + nb * 8 + (lane >> 2);
                        uint32_t b0 = Ws[cn][kb];
                        uint32_t b1 = Ws[cn][kb + 4];
#pragma unroll
                        for (int ma = 0; ma < 4; ma++)
                            mma8(acc[ma][nb][0], acc[ma][nb][1], acc[ma][nb][2], acc[ma][nb][3],
                                 af[ma][0], af[ma][1], af[ma][2], af[ma][3], b0, b1);
                    }
                }
                __syncthreads();
            }
        }

        // epilogue: + gpre, gate exchange, cell update (c in SMEM), write h[t]
        const float* gp = gpre + (size_t)t * batch * 512;
        float* hrow = hout + (size_t)t * batch * 128;
#pragma unroll
        for (int ma = 0; ma < 4; ma++) {
#pragma unroll
            for (int nb = 0; nb < 4; nb++) {
#pragma unroll
                for (int hh = 0; hh < 2; hh++) {
                    int mloc = wm + ma * 16 + (lane >> 2) + hh * 8;
                    int mh = m0 + mloc;
                    int jl = wn + nb * 8 + (lane & 3) * 2;
                    int jg = nq * 128 + jl;
                    float g0 = acc[ma][nb][hh*2]     + gp[(size_t)mh * 512 + jg];
                    float g1 = acc[ma][nb][hh*2 + 1] + gp[(size_t)mh * 512 + jg + 1];
                    float p0 = __shfl_xor_sync(0xffffffffu, g0, 1);
                    float p1 = __shfl_xor_sync(0xffffffffu, g1, 1);
                    if (!(lane & 1)) {
                        int cl = jl >> 2;   // cell within quadrant, 0..31
                        float cold = c_s[mloc * 33 + cl];
                        float cn = sigm(g1) * cold + sigm(g0) * tanhf(p0);
                        float hn = sigm(p1) * tanhf(cn);
                        c_s[mloc * 33 + cl] = cn;
                        hrow[(size_t)mh * 128 + nq * 32 + cl] = hn;
                    }
                }
            }
        }
        if (t < T - 1) grid_sync_();
    }
}

// ---------------- concat fwd/bwd hidden states ----------------
__global__ void hcat_tok(const float* __restrict__ hf, const float* __restrict__ hb,
                         const int* __restrict__ toklen, float* __restrict__ hcat) {
    size_t idx = (size_t)blockIdx.x * 256 + threadIdx.x;
    int k = (int)(idx & 127);
    size_t row = idx >> 7;
    int n = (int)(row & (NU-1));
    int t = (int)(row >> 12);
    int len = toklen[n];
    bool valid = t < len;
    int rev = len - 1 - t;
    rev = rev < 0 ? 0 : (rev > T_TOK-1 ? T_TOK-1 : rev);
    float vf = valid ? hf[idx] : 0.f;
    float vb = valid ? hb[((size_t)(rev*NU + n))*128 + k] : 0.f;
    hcat[row*256 + k]       = vf;
    hcat[row*256 + 128 + k] = vb;
}

__global__ void hcat_path(const float* __restrict__ hpf, const float* __restrict__ hpb,
                          const int* __restrict__ plen, float* __restrict__ hcatp) {
    size_t idx = (size_t)blockIdx.x * 256 + threadIdx.x;
    int k = (int)(idx & 127);
    size_t row = idx >> 7;
    int p = (int)(row & (NP-1));
    int l = (int)(row >> 10);
    int pl = plen[p];
    bool valid = l < pl;
    int rev = pl - 1 - l;
    rev = rev < 0 ? 0 : (rev > LP-1 ? LP-1 : rev);
    float vf = valid ? hpf[idx] : 0.f;
    float vb = valid ? hpb[((size_t)(rev*NP + p))*128 + k] : 0.f;
    hcatp[row*256 + k]       = vf;
    hcatp[row*256 + 128 + k] = vb;
}

// ---------------- attention ----------------
__device__ __forceinline__ float blk_sum128(float v, float* r4) {
#pragma unroll
    for (int o = 16; o > 0; o >>= 1) v += __shfl_xor_sync(0xffffffffu, v, o);
    __syncthreads();
    if ((threadIdx.x & 31) == 0) r4[threadIdx.x >> 5] = v;
    __syncthreads();
    return r4[0] + r4[1] + r4[2] + r4[3];
}

__global__ void attn_kernel(const float* __restrict__ outlin, const int* __restrict__ toklen,
                            const float* __restrict__ ln_g, const float* __restrict__ ln_b,
                            const float* __restrict__ attn_w, const float* __restrict__ attn_b,
                            float* __restrict__ tokfeat) {
    int n = blockIdx.x, e = threadIdx.x;
    __shared__ float r4[4];
    __shared__ float sc[T_TOK];
    int len = toklen[n];
    float g = ln_g[e], bb = ln_b[e], aw = attn_w[e], ab = attn_b[0];
    float xv[T_TOK];
    for (int t = 0; t < T_TOK; t++) {
        float x = outlin[((size_t)(t*NU + n))*128 + e];
        xv[t] = x;
        float m = blk_sum128(x, r4) * (1.f/128.f);
        float d = x - m;
        float v = blk_sum128(d*d, r4) * (1.f/128.f);
        float q = tanhf(d * rsqrtf(v + 1e-5f) * g + bb);
        float s = blk_sum128(q * aw, r4);
        if (e == 0) sc[t] = (t < len) ? (s + ab) : -1e9f;
    }
    __syncthreads();
    float mx = -3.4e38f;
#pragma unroll
    for (int t = 0; t < T_TOK; t++) mx = fmaxf(mx, sc[t]);
    float ww[T_TOK]; float den = 0.f;
#pragma unroll
    for (int t = 0; t < T_TOK; t++) { ww[t] = expf(sc[t] - mx); den += ww[t]; }
    float inv = 1.f / den;
    float acc = 0.f;
#pragma unroll
    for (int t = 0; t < T_TOK; t++) acc += ww[t] * inv * xv[t];
    tokfeat[(size_t)n*128 + e] = acc;
}

// ---------------- host ----------------
extern "C" void kernel_launch(void* const* d_in, const int* in_sizes, int n_in,
                              void* d_out, int out_size) {
    const int*   units   = (const int*)d_in[0];
    const int*   paths   = (const int*)d_in[1];
    const int*   upd     = (const int*)d_in[2];
    const int*   ppd     = (const int*)d_in[3];
    const float* emb     = (const float*)d_in[4];
    const float* tl_Wif  = (const float*)d_in[5];
    const float* tl_Whf  = (const float*)d_in[6];
    const float* tl_bf   = (const float*)d_in[7];
    const float* tl_Wib  = (const float*)d_in[8];
    const float* tl_Whb  = (const float*)d_in[9];
    const float* tl_bb   = (const float*)d_in[10];
    const float* lin_W   = (const float*)d_in[11];
    const float* lin_b   = (const float*)d_in[12];
    const float* ln_g    = (const float*)d_in[13];
    const float* ln_bb   = (const float*)d_in[14];
    const float* attn_w  = (const float*)d_in[15];
    const float* attn_b  = (const float*)d_in[16];
    const float* pl_Wif  = (const float*)d_in[17];
    const float* pl_Whf  = (const float*)d_in[18];
    const float* pl_bf   = (const float*)d_in[19];
    const float* pl_Wib  = (const float*)d_in[20];
    const float* pl_Whb  = (const float*)d_in[21];
    const float* pl_bb   = (const float*)d_in[22];
    const float* ul_W    = (const float*)d_in[23];
    const float* ul_b    = (const float*)d_in[24];
    float* out = (float*)d_out;

    float *gpre_f, *gpre_b, *hf, *hb, *hcat, *outlin, *tokfeat;
    float *gpre_pf, *gpre_pb, *hpf, *hpb, *hcatp;
    int *toklen, *rm_tb, *rm_pf, *rm_pb, *plen;
    cudaGetSymbolAddress((void**)&gpre_f,  g_gpre_f);
    cudaGetSymbolAddress((void**)&gpre_b,  g_gpre_b);
    cudaGetSymbolAddress((void**)&hf,      g_hf);
    cudaGetSymbolAddress((void**)&hb,      g_hb);
    cudaGetSymbolAddress((void**)&hcat,    g_hcat);
    cudaGetSymbolAddress((void**)&outlin,  g_outlin);
    cudaGetSymbolAddress((void**)&tokfeat, g_tokfeat);
    cudaGetSymbolAddress((void**)&gpre_pf, g_gpre_pf);
    cudaGetSymbolAddress((void**)&gpre_pb, g_gpre_pb);
    cudaGetSymbolAddress((void**)&hpf,     g_hpf);
    cudaGetSymbolAddress((void**)&hpb,     g_hpb);
    cudaGetSymbolAddress((void**)&hcatp,   g_hcatp);
    cudaGetSymbolAddress((void**)&toklen,  g_toklen);
    cudaGetSymbolAddress((void**)&rm_tb,   g_rm_tb);
    cudaGetSymbolAddress((void**)&rm_pf,   g_rm_pf);
    cudaGetSymbolAddress((void**)&rm_pb,   g_rm_pb);
    cudaGetSymbolAddress((void**)&plen,    g_plen);

    cudaFuncSetAttribute(lstm_persist, cudaFuncAttributeMaxDynamicSharedMemorySize,
                         PERSIST_SMEM);

    prep_tok<<<(NU+255)/256, 256>>>(units, toklen, rm_tb);

    // token input-gate GEMMs (tf32 mma, gate-interleaved output)
    mma_gemm<<<dim3(4, T_TOK*NU/128), 256>>>(emb, units, tl_Wif, tl_bf, gpre_f, T_TOK*NU, G4, E, 1);
    mma_gemm<<<dim3(4, T_TOK*NU/128), 256>>>(emb, rm_tb, tl_Wib, tl_bb, gpre_b, T_TOK*NU, G4, E, 1);

    // token recurrence: one persistent launch, 256 co-resident CTAs
    lstm_persist<<<(NU/128)*4*2, 256, PERSIST_SMEM>>>(
        gpre_f, gpre_b, hf, hb, tl_Whf, tl_Whb, NU, T_TOK);

    hcat_tok<<<(int)((size_t)T_TOK*NU*H/256), 256>>>(hf, hb, toklen, hcat);
    mma_gemm<<<dim3(1, T_TOK*NU/128), 256>>>(hcat, nullptr, lin_W, lin_b, outlin, T_TOK*NU, E, 2*H, 0);
    attn_kernel<<<NU, 128>>>(outlin, toklen, ln_g, ln_bb, attn_w, attn_b, tokfeat);

    // path side
    prep_path<<<(NP+255)/256, 256>>>(paths, upd, ppd, plen, rm_pf, rm_pb);
    mma_gemm<<<dim3(4, LP*NP/128), 256>>>(tokfeat, rm_pf, pl_Wif, pl_bf, gpre_pf, LP*NP, G4, E, 1);
    mma_gemm<<<dim3(4, LP*NP/128), 256>>>(tokfeat, rm_pb, pl_Wib, pl_bb, gpre_pb, LP*NP, G4, E, 1);

    // path recurrence: 64 co-resident CTAs
    lstm_persist<<<(NP/128)*4*2, 256, PERSIST_SMEM>>>(
        gpre_pf, gpre_pb, hpf, hpb, pl_Whf, pl_Whb, NP, LP);

    hcat_path<<<(int)((size_t)LP*NP*H/256), 256>>>(hpf, hpb, plen, hcatp);
    mma_gemm<<<dim3(1, LP*NP/128), 256>>>(hcatp, nullptr, ul_W, ul_b, out, LP*NP, E, 2*H, 0);
}

// round 11
// speedup vs baseline: 1.3013x; 1.0766x over previous
#include <cuda_runtime.h>
#include <cuda_fp16.h>
#include <math.h>
#include <stdint.h>

#define T_TOK 16
#define NU    4096
#define E     128
#define H     128
#define LP    32
#define NP    1024
#define G4    512   // 4*H

// ---------------- scratch (static device memory; allocation-free) ----------------
__device__ __align__(16) __half g_gpre_f[(size_t)T_TOK*NU*G4];   // gate-interleaved, fp16
__device__ __align__(16) __half g_gpre_b[(size_t)T_TOK*NU*G4];
__device__ __align__(16) float g_hf[(size_t)T_TOK*NU*H];
__device__ __align__(16) float g_hb[(size_t)T_TOK*NU*H];
__device__ __align__(16) float g_hcat[(size_t)T_TOK*NU*2*H];
__device__ __align__(16) float g_outlin[(size_t)T_TOK*NU*E];
__device__ __align__(16) float g_tokfeat[NU*E];
__device__ int   g_toklen[NU];
__device__ int   g_rm_tb[T_TOK*NU];
__device__ int   g_rm_pf[LP*NP];
__device__ int   g_rm_pb[LP*NP];
__device__ int   g_plen[NP];
__device__ __align__(16) __half g_gpre_pf[(size_t)LP*NP*G4];
__device__ __align__(16) __half g_gpre_pb[(size_t)LP*NP*G4];
__device__ __align__(16) float g_hpf[(size_t)LP*NP*H];
__device__ __align__(16) float g_hpb[(size_t)LP*NP*H];
__device__ __align__(16) float g_hcatp[(size_t)LP*NP*2*H];

// software grid barrier state (self-resetting; monotone generation)
__device__ unsigned g_bcnt = 0;
__device__ unsigned g_bgen = 0;

__device__ __forceinline__ float sigm(float x) { return 1.f / (1.f + expf(-x)); }

// ---------------- tf32 mma.sync helpers ----------------
__device__ __forceinline__ uint32_t f2tf(float f) {
    uint32_t r; asm("cvt.rna.tf32.f32 %0, %1;" : "=r"(r) : "f"(f)); return r;
}
__device__ __forceinline__ void mma8(float& d0, float& d1, float& d2, float& d3,
                                     uint32_t a0, uint32_t a1, uint32_t a2, uint32_t a3,
                                     uint32_t b0, uint32_t b1) {
    asm volatile(
        "mma.sync.aligned.m16n8k8.row.col.f32.tf32.tf32.f32 "
        "{%0,%1,%2,%3}, {%4,%5,%6,%7}, {%8,%9}, {%0,%1,%2,%3};"
        : "+f"(d0), "+f"(d1), "+f"(d2), "+f"(d3)
        : "r"(a0), "r"(a1), "r"(a2), "r"(a3), "r"(b0), "r"(b1));
}
// gate interleave: output col j <- original weight row (j&3)*128 + (j>>2)
__device__ __forceinline__ int gperm(int j) { return (j & 3) * 128 + (j >> 2); }

__device__ __forceinline__ void grid_sync_() {
    __syncthreads();
    if (threadIdx.x == 0) {
        __threadfence();
        unsigned gen = *((volatile unsigned*)&g_bgen);
        unsigned n = gridDim.x;
        if (atomicAdd(&g_bcnt, 1) == n - 1) {
            *((volatile unsigned*)&g_bcnt) = 0;
            __threadfence();
            atomicExch(&g_bgen, gen + 1);
        } else {
            while (*((volatile unsigned*)&g_bgen) == gen) { }
        }
        __threadfence();
    }
    __syncthreads();
}

// ---------------- prep: token lengths + backward-input row map ----------------
__global__ void prep_tok(const int* __restrict__ units, int* __restrict__ toklen,
                         int* __restrict__ rm_b) {
    int n = blockIdx.x * blockDim.x + threadIdx.x;
    if (n >= NU) return;
    int len = T_TOK;
    for (int t = 0; t < T_TOK; t++)
        if (units[t*NU + n] == 0) { len = t; break; }
    toklen[n] = len;
    for (int s = 0; s < T_TOK; s++) {
        int st = len - 1 - s;
        st = st < 0 ? 0 : (st > T_TOK-1 ? T_TOK-1 : st);
        rm_b[s*NU + n] = units[st*NU + n];
    }
}

// ---------------- prep: path lengths + gather row maps ----------------
__global__ void prep_path(const int* __restrict__ paths, const int* __restrict__ upd,
                          const int* __restrict__ ppd, int* __restrict__ plen_out,
                          int* __restrict__ rm_f, int* __restrict__ rm_b) {
    int p = blockIdx.x * blockDim.x + threadIdx.x;
    if (p >= NP) return;
    int d = 0, cum = 0;
    for (int i = 0; i < 8; i++) { int c = ppd[i]; if (p < cum + c) { d = i; break; } cum += c; }
    int off = 0;
    for (int i = 0; i < d; i++) off += upd[i];
    int un = upd[d];
    int fe = LP;
    for (int l = 0; l < LP; l++)
        if (paths[l*NP + p] == -1) { fe = l; break; }
    int plen = LP;
    for (int l = 0; l < LP; l++) {
        int pv = paths[l*NP + p];
        bool m = (l < fe) ? (pv < 0 || pv > un) : true;
        if (m) { plen = l; break; }
    }
    plen_out[p] = plen;
    for (int l = 0; l < LP; l++) {
        int pv = paths[l*NP + p];
        bool keep = (l < fe) && pv >= 0 && pv < un;
        int pvc = pv < 0 ? 0 : pv;
        int gidx = pvc + off; if (gidx > NU-1) gidx = NU-1;
        rm_f[l*NP + p] = keep ? gidx : -1;
    }
    for (int s = 0; s < LP; s++) {
        int sl = plen - 1 - s;
        sl = sl < 0 ? 0 : (sl > LP-1 ? LP-1 : sl);
        int pv = paths[sl*NP + p];
        bool keep = (sl < fe) && pv >= 0 && pv < un;
        int pvc = pv < 0 ? 0 : pv;
        int gidx = pvc + off; if (gidx > NU-1) gidx = NU-1;
        rm_b[s*NP + p] = keep ? gidx : -1;
    }
}

// ===================== tf32 mma.sync GEMM =====================
// C[m][j] = bias[pj] + sum_k Arow(m)[k] * B[pj][k],  pj = permB ? gperm(j) : j
// outHalf: C is __half (gate GEMMs) else float.
__global__ __launch_bounds__(256) void mma_gemm(
    const float* __restrict__ A, const int* __restrict__ rowmap,
    const float* __restrict__ B, const float* __restrict__ bias,
    void* __restrict__ Cv, int M, int N, int K, int permB, int outHalf)
{
    __shared__ uint32_t As[128][36];
    __shared__ uint32_t Bs[128][36];
    __shared__ int rid[128];
    int tid = threadIdx.x, lane = tid & 31, wid = tid >> 5;
    int wm = (wid >> 2) * 64, wn = (wid & 3) * 32;
    int m0 = blockIdx.y * 128, n0 = blockIdx.x * 128;
    if (tid < 128) rid[tid] = rowmap ? rowmap[m0 + tid] : (m0 + tid);
    float acc[4][4][4];
#pragma unroll
    for (int a = 0; a < 4; a++)
#pragma unroll
        for (int b = 0; b < 4; b++)
#pragma unroll
            for (int q = 0; q < 4; q++) acc[a][b][q] = 0.f;
    __syncthreads();

    for (int kc = 0; kc < K; kc += 32) {
        for (int i = tid; i < 1024; i += 256) {
            int r = i >> 3, q = i & 7;
            int src = rid[r];
            float4 v = make_float4(0.f, 0.f, 0.f, 0.f);
            if (src >= 0) v = *(const float4*)(A + (size_t)src * K + kc + q * 4);
            As[r][q*4+0] = f2tf(v.x); As[r][q*4+1] = f2tf(v.y);
            As[r][q*4+2] = f2tf(v.z); As[r][q*4+3] = f2tf(v.w);
        }
        for (int i = tid; i < 1024; i += 256) {
            int r = i >> 3, q = i & 7;
            int srcr = permB ? gperm(n0 + r) : (n0 + r);
            float4 v = *(const float4*)(B + (size_t)srcr * K + kc + q * 4);
            Bs[r][q*4+0] = f2tf(v.x); Bs[r][q*4+1] = f2tf(v.y);
            Bs[r][q*4+2] = f2tf(v.z); Bs[r][q*4+3] = f2tf(v.w);
        }
        __syncthreads();
#pragma unroll
        for (int ks = 0; ks < 4; ks++) {
            int kc4 = ks * 8 + (lane & 3);
            uint32_t af[4][4];
#pragma unroll
            for (int ma = 0; ma < 4; ma++) {
                int r = wm + ma * 16 + (lane >> 2);
                af[ma][0] = As[r    ][kc4];
                af[ma][1] = As[r + 8][kc4];
                af[ma][2] = As[r    ][kc4 + 4];
                af[ma][3] = As[r + 8][kc4 + 4];
            }
#pragma unroll
            for (int nb = 0; nb < 4; nb++) {
                int cn = wn + nb * 8 + (lane >> 2);
                uint32_t b0 = Bs[cn][kc4];
                uint32_t b1 = Bs[cn][kc4 + 4];
#pragma unroll
                for (int ma = 0; ma < 4; ma++)
                    mma8(acc[ma][nb][0], acc[ma][nb][1], acc[ma][nb][2], acc[ma][nb][3],
                         af[ma][0], af[ma][1], af[ma][2], af[ma][3], b0, b1);
            }
        }
        __syncthreads();
    }
#pragma unroll
    for (int ma = 0; ma < 4; ma++) {
        int m = m0 + wm + ma * 16 + (lane >> 2);
#pragma unroll
        for (int nb = 0; nb < 4; nb++) {
            int j = n0 + wn + nb * 8 + (lane & 3) * 2;
            float b0v = bias[permB ? gperm(j)     : j];
            float b1v = bias[permB ? gperm(j + 1) : j + 1];
            if (outHalf) {
                __half* C = (__half*)Cv;
                *(__half2*)(C + (size_t)m * N + j) =
                    __floats2half2_rn(acc[ma][nb][0] + b0v, acc[ma][nb][1] + b1v);
                *(__half2*)(C + (size_t)(m + 8) * N + j) =
                    __floats2half2_rn(acc[ma][nb][2] + b0v, acc[ma][nb][3] + b1v);
            } else {
                float* C = (float*)Cv;
                *(float2*)(C + (size_t)m * N + j) =
                    make_float2(acc[ma][nb][0] + b0v, acc[ma][nb][1] + b1v);
                *(float2*)(C + (size_t)(m + 8) * N + j) =
                    make_float2(acc[ma][nb][2] + b0v, acc[ma][nb][3] + b1v);
            }
        }
    }
}

// ===================== persistent BiLSTM recurrence =====================
// CTA owns (dir, m-slice of 128, gate quadrant of 128). Wh quadrant resident in
// SMEM (tf32); c resident in SMEM; steps separated by software grid barrier.
#define SM_WS 0
#define SM_AS 67584                       // Ws: 128 x 132 u32
#define SM_CS (67584 + 18432)             // As: 128 x 36 u32
#define PERSIST_SMEM (67584 + 18432 + 16896)   // c:  128 x 33 f32

__global__ __launch_bounds__(256, 2) void lstm_persist(
    const __half* __restrict__ gpre_f, const __half* __restrict__ gpre_b,
    float* __restrict__ hf_, float* __restrict__ hb_,
    const float* __restrict__ Whf, const float* __restrict__ Whb,
    int batch, int T)
{
    extern __shared__ char smch[];
    uint32_t (*Ws)[132] = (uint32_t (*)[132])(smch + SM_WS);
    uint32_t (*As)[36]  = (uint32_t (*)[36])(smch + SM_AS);
    float* c_s = (float*)(smch + SM_CS);

    int mblocks = batch >> 7;
    int bid = blockIdx.x;
    int dir = bid / (mblocks * 4);
    int rem = bid % (mblocks * 4);
    int mq = rem >> 2, nq = rem & 3;
    const __half* gpre = dir ? gpre_b : gpre_f;
    float*        hout = dir ? hb_    : hf_;
    const float*  Wh   = dir ? Whb    : Whf;

    int tid = threadIdx.x, lane = tid & 31, wid = tid >> 5;
    int wm = (wid >> 2) * 64, wn = (wid & 3) * 32;
    int m0 = mq * 128;

    for (int i = tid; i < 4096; i += 256) {
        int r = i >> 5, q = i & 31;
        float4 v = *(const float4*)(Wh + (size_t)gperm(nq * 128 + r) * 128 + q * 4);
        Ws[r][q*4+0] = f2tf(v.x); Ws[r][q*4+1] = f2tf(v.y);
        Ws[r][q*4+2] = f2tf(v.z); Ws[r][q*4+3] = f2tf(v.w);
    }
    for (int i = tid; i < 128 * 33; i += 256) c_s[i] = 0.f;
    __syncthreads();

    for (int t = 0; t < T; t++) {
        float acc[4][4][4];
#pragma unroll
        for (int x = 0; x < 4; x++)
#pragma unroll
            for (int y = 0; y < 4; y++)
#pragma unroll
                for (int q = 0; q < 4; q++) acc[x][y][q] = 0.f;

        if (t > 0) {
            const float* hprev = hout + (size_t)(t - 1) * batch * 128;
            for (int kc = 0; kc < 128; kc += 32) {
                for (int i = tid; i < 1024; i += 256) {
                    int r = i >> 3, q = i & 7;
                    float4 v = *(const float4*)(hprev + (size_t)(m0 + r) * 128 + kc + q * 4);
                    As[r][q*4+0] = f2tf(v.x); As[r][q*4+1] = f2tf(v.y);
                    As[r][q*4+2] = f2tf(v.z); As[r][q*4+3] = f2tf(v.w);
                }
                __syncthreads();
#pragma unroll
                for (int ks = 0; ks < 4; ks++) {
                    int ka = ks * 8 + (lane & 3);
                    int kb = kc + ka;
                    uint32_t af[4][4];
#pragma unroll
                    for (int ma = 0; ma < 4; ma++) {
                        int r = wm + ma * 16 + (lane >> 2);
                        af[ma][0] = As[r    ][ka];
                        af[ma][1] = As[r + 8][ka];
                        af[ma][2] = As[r    ][ka + 4];
                        af[ma][3] = As[r + 8][ka + 4];
                    }
#pragma unroll
                    for (int nb = 0; nb < 4; nb++) {
                        int cn = wn + nb * 8 + (lane >> 2);
                        uint32_t b0 = Ws[cn][kb];
                        uint32_t b1 = Ws[cn][kb + 4];
#pragma unroll
                        for (int ma = 0; ma < 4; ma++)
                            mma8(acc[ma][nb][0], acc[ma][nb][1], acc[ma][nb][2], acc[ma][nb][3],
                                 af[ma][0], af[ma][1], af[ma][2], af[ma][3], b0, b1);
                    }
                }
                __syncthreads();
            }
        }

        const __half* gp = gpre + (size_t)t * batch * 512;
        float* hrow = hout + (size_t)t * batch * 128;
#pragma unroll
        for (int ma = 0; ma < 4; ma++) {
#pragma unroll
            for (int nb = 0; nb < 4; nb++) {
#pragma unroll
                for (int hh = 0; hh < 2; hh++) {
                    int mloc = wm + ma * 16 + (lane >> 2) + hh * 8;
                    int mh = m0 + mloc;
                    int jl = wn + nb * 8 + (lane & 3) * 2;
                    int jg = nq * 128 + jl;
                    __half2 gv = *(const __half2*)(gp + (size_t)mh * 512 + jg);
                    float2 gf2 = __half22float2(gv);
                    float g0 = acc[ma][nb][hh*2]     + gf2.x;
                    float g1 = acc[ma][nb][hh*2 + 1] + gf2.y;
                    float p0 = __shfl_xor_sync(0xffffffffu, g0, 1);
                    float p1 = __shfl_xor_sync(0xffffffffu, g1, 1);
                    if (!(lane & 1)) {
                        int cl = jl >> 2;
                        float cold = c_s[mloc * 33 + cl];
                        float cn = sigm(g1) * cold + sigm(g0) * tanhf(p0);
                        float hn = sigm(p1) * tanhf(cn);
                        c_s[mloc * 33 + cl] = cn;
                        hrow[(size_t)mh * 128 + nq * 32 + cl] = hn;
                    }
                }
            }
        }
        if (t < T - 1) grid_sync_();
    }
}

// ---------------- concat fwd/bwd hidden states ----------------
__global__ void hcat_tok(const float* __restrict__ hf, const float* __restrict__ hb,
                         const int* __restrict__ toklen, float* __restrict__ hcat) {
    size_t idx = (size_t)blockIdx.x * 256 + threadIdx.x;
    int k = (int)(idx & 127);
    size_t row = idx >> 7;
    int n = (int)(row & (NU-1));
    int t = (int)(row >> 12);
    int len = toklen[n];
    bool valid = t < len;
    int rev = len - 1 - t;
    rev = rev < 0 ? 0 : (rev > T_TOK-1 ? T_TOK-1 : rev);
    float vf = valid ? hf[idx] : 0.f;
    float vb = valid ? hb[((size_t)(rev*NU + n))*128 + k] : 0.f;
    hcat[row*256 + k]       = vf;
    hcat[row*256 + 128 + k] = vb;
}

__global__ void hcat_path(const float* __restrict__ hpf, const float* __restrict__ hpb,
                          const int* __restrict__ plen, float* __restrict__ hcatp) {
    size_t idx = (size_t)blockIdx.x * 256 + threadIdx.x;
    int k = (int)(idx & 127);
    size_t row = idx >> 7;
    int p = (int)(row & (NP-1));
    int l = (int)(row >> 10);
    int pl = plen[p];
    bool valid = l < pl;
    int rev = pl - 1 - l;
    rev = rev < 0 ? 0 : (rev > LP-1 ? LP-1 : rev);
    float vf = valid ? hpf[idx] : 0.f;
    float vb = valid ? hpb[((size_t)(rev*NP + p))*128 + k] : 0.f;
    hcatp[row*256 + k]       = vf;
    hcatp[row*256 + 128 + k] = vb;
}

// ---------------- attention ----------------
__device__ __forceinline__ float blk_sum128(float v, float* r4) {
#pragma unroll
    for (int o = 16; o > 0; o >>= 1) v += __shfl_xor_sync(0xffffffffu, v, o);
    __syncthreads();
    if ((threadIdx.x & 31) == 0) r4[threadIdx.x >> 5] = v;
    __syncthreads();
    return r4[0] + r4[1] + r4[2] + r4[3];
}

__global__ void attn_kernel(const float* __restrict__ outlin, const int* __restrict__ toklen,
                            const float* __restrict__ ln_g, const float* __restrict__ ln_b,
                            const float* __restrict__ attn_w, const float* __restrict__ attn_b,
                            float* __restrict__ tokfeat) {
    int n = blockIdx.x, e = threadIdx.x;
    __shared__ float r4[4];
    __shared__ float sc[T_TOK];
    int len = toklen[n];
    float g = ln_g[e], bb = ln_b[e], aw = attn_w[e], ab = attn_b[0];
    float xv[T_TOK];
    for (int t = 0; t < T_TOK; t++) {
        float x = outlin[((size_t)(t*NU + n))*128 + e];
        xv[t] = x;
        float m = blk_sum128(x, r4) * (1.f/128.f);
        float d = x - m;
        float v = blk_sum128(d*d, r4) * (1.f/128.f);
        float q = tanhf(d * rsqrtf(v + 1e-5f) * g + bb);
        float s = blk_sum128(q * aw, r4);
        if (e == 0) sc[t] = (t < len) ? (s + ab) : -1e9f;
    }
    __syncthreads();
    float mx = -3.4e38f;
#pragma unroll
    for (int t = 0; t < T_TOK; t++) mx = fmaxf(mx, sc[t]);
    float ww[T_TOK]; float den = 0.f;
#pragma unroll
    for (int t = 0; t < T_TOK; t++) { ww[t] = expf(sc[t] - mx); den += ww[t]; }
    float inv = 1.f / den;
    float acc = 0.f;
#pragma unroll
    for (int t = 0; t < T_TOK; t++) acc += ww[t] * inv * xv[t];
    tokfeat[(size_t)n*128 + e] = acc;
}

// ---------------- host ----------------
extern "C" void kernel_launch(void* const* d_in, const int* in_sizes, int n_in,
                              void* d_out, int out_size) {
    const int*   units   = (const int*)d_in[0];
    const int*   paths   = (const int*)d_in[1];
    const int*   upd     = (const int*)d_in[2];
    const int*   ppd     = (const int*)d_in[3];
    const float* emb     = (const float*)d_in[4];
    const float* tl_Wif  = (const float*)d_in[5];
    const float* tl_Whf  = (const float*)d_in[6];
    const float* tl_bf   = (const float*)d_in[7];
    const float* tl_Wib  = (const float*)d_in[8];
    const float* tl_Whb  = (const float*)d_in[9];
    const float* tl_bb   = (const float*)d_in[10];
    const float* lin_W   = (const float*)d_in[11];
    const float* lin_b   = (const float*)d_in[12];
    const float* ln_g    = (const float*)d_in[13];
    const float* ln_bb   = (const float*)d_in[14];
    const float* attn_w  = (const float*)d_in[15];
    const float* attn_b  = (const float*)d_in[16];
    const float* pl_Wif  = (const float*)d_in[17];
    const float* pl_Whf  = (const float*)d_in[18];
    const float* pl_bf   = (const float*)d_in[19];
    const float* pl_Wib  = (const float*)d_in[20];
    const float* pl_Whb  = (const float*)d_in[21];
    const float* pl_bb   = (const float*)d_in[22];
    const float* ul_W    = (const float*)d_in[23];
    const float* ul_b    = (const float*)d_in[24];
    float* out = (float*)d_out;

    __half *gpre_f, *gpre_b, *gpre_pf, *gpre_pb;
    float *hf, *hb, *hcat, *outlin, *tokfeat, *hpf, *hpb, *hcatp;
    int *toklen, *rm_tb, *rm_pf, *rm_pb, *plen;
    cudaGetSymbolAddress((void**)&gpre_f,  g_gpre_f);
    cudaGetSymbolAddress((void**)&gpre_b,  g_gpre_b);
    cudaGetSymbolAddress((void**)&hf,      g_hf);
    cudaGetSymbolAddress((void**)&hb,      g_hb);
    cudaGetSymbolAddress((void**)&hcat,    g_hcat);
    cudaGetSymbolAddress((void**)&outlin,  g_outlin);
    cudaGetSymbolAddress((void**)&tokfeat, g_tokfeat);
    cudaGetSymbolAddress((void**)&gpre_pf, g_gpre_pf);
    cudaGetSymbolAddress((void**)&gpre_pb, g_gpre_pb);
    cudaGetSymbolAddress((void**)&hpf,     g_hpf);
    cudaGetSymbolAddress((void**)&hpb,     g_hpb);
    cudaGetSymbolAddress((void**)&hcatp,   g_hcatp);
    cudaGetSymbolAddress((void**)&toklen,  g_toklen);
    cudaGetSymbolAddress((void**)&rm_tb,   g_rm_tb);
    cudaGetSymbolAddress((void**)&rm_pf,   g_rm_pf);
    cudaGetSymbolAddress((void**)&rm_pb,   g_rm_pb);
    cudaGetSymbolAddress((void**)&plen,    g_plen);

    cudaFuncSetAttribute(lstm_persist, cudaFuncAttributeMaxDynamicSharedMemorySize,
                         PERSIST_SMEM);

    prep_tok<<<(NU+255)/256, 256>>>(units, toklen, rm_tb);

    // token input-gate GEMMs (tf32 mma, gate-interleaved fp16 output)
    mma_gemm<<<dim3(4, T_TOK*NU/128), 256>>>(emb, units, tl_Wif, tl_bf, gpre_f, T_TOK*NU, G4, E, 1, 1);
    mma_gemm<<<dim3(4, T_TOK*NU/128), 256>>>(emb, rm_tb, tl_Wib, tl_bb, gpre_b, T_TOK*NU, G4, E, 1, 1);

    // token recurrence: one persistent launch, 256 co-resident CTAs
    lstm_persist<<<(NU/128)*4*2, 256, PERSIST_SMEM>>>(
        gpre_f, gpre_b, hf, hb, tl_Whf, tl_Whb, NU, T_TOK);

    hcat_tok<<<(int)((size_t)T_TOK*NU*H/256), 256>>>(hf, hb, toklen, hcat);
    mma_gemm<<<dim3(1, T_TOK*NU/128), 256>>>(hcat, nullptr, lin_W, lin_b, outlin, T_TOK*NU, E, 2*H, 0, 0);
    attn_kernel<<<NU, 128>>>(outlin, toklen, ln_g, ln_bb, attn_w, attn_b, tokfeat);

    // path side
    prep_path<<<(NP+255)/256, 256>>>(paths, upd, ppd, plen, rm_pf, rm_pb);
    mma_gemm<<<dim3(4, LP*NP/128), 256>>>(tokfeat, rm_pf, pl_Wif, pl_bf, gpre_pf, LP*NP, G4, E, 1, 1);
    mma_gemm<<<dim3(4, LP*NP/128), 256>>>(tokfeat, rm_pb, pl_Wib, pl_bb, gpre_pb, LP*NP, G4, E, 1, 1);

    // path recurrence: 64 co-resident CTAs
    lstm_persist<<<(NP/128)*4*2, 256, PERSIST_SMEM>>>(
        gpre_pf, gpre_pb, hpf, hpb, pl_Whf, pl_Whb, NP, LP);

    hcat_path<<<(int)((size_t)LP*NP*H/256), 256>>>(hpf, hpb, plen, hcatp);
    mma_gemm<<<dim3(1, LP*NP/128), 256>>>(hcatp, nullptr, ul_W, ul_b, out, LP*NP, E, 2*H, 0, 0);
}

// round 12
// speedup vs baseline: 1.6716x; 1.2846x over previous
#include <cuda_runtime.h>
#include <cuda_fp16.h>
#include <math.h>
#include <stdint.h>

#define T_TOK 16
#define NU    4096
#define E     128
#define H     128
#define LP    32
#define NP    1024
#define G4    512   // 4*H

// ---------------- scratch (static device memory; allocation-free) ----------------
__device__ __align__(16) __half g_gpre_f[(size_t)T_TOK*NU*G4];   // gate-interleaved, fp16
__device__ __align__(16) __half g_gpre_b[(size_t)T_TOK*NU*G4];
__device__ __align__(16) float g_hf[(size_t)T_TOK*NU*H];
__device__ __align__(16) float g_hb[(size_t)T_TOK*NU*H];
__device__ __align__(16) float g_hcat[(size_t)T_TOK*NU*2*H];
__device__ __align__(16) float g_outlin[(size_t)T_TOK*NU*E];
__device__ __align__(16) float g_tokfeat[NU*E];
__device__ int   g_toklen[NU];
__device__ int   g_rm_tb[T_TOK*NU];
__device__ int   g_rm_pf[LP*NP];
__device__ int   g_rm_pb[LP*NP];
__device__ int   g_plen[NP];
__device__ __align__(16) __half g_gpre_pf[(size_t)LP*NP*G4];
__device__ __align__(16) __half g_gpre_pb[(size_t)LP*NP*G4];
__device__ __align__(16) float g_hpf[(size_t)LP*NP*H];
__device__ __align__(16) float g_hpb[(size_t)LP*NP*H];
__device__ __align__(16) float g_hcatp[(size_t)LP*NP*2*H];

__device__ __forceinline__ float sigm(float x) { return 1.f / (1.f + expf(-x)); }

// ---------------- mma helpers ----------------
__device__ __forceinline__ uint32_t f2tf(float f) {
    uint32_t r; asm("cvt.rna.tf32.f32 %0, %1;" : "=r"(r) : "f"(f)); return r;
}
__device__ __forceinline__ void mma8(float& d0, float& d1, float& d2, float& d3,
                                     uint32_t a0, uint32_t a1, uint32_t a2, uint32_t a3,
                                     uint32_t b0, uint32_t b1) {
    asm volatile(
        "mma.sync.aligned.m16n8k8.row.col.f32.tf32.tf32.f32 "
        "{%0,%1,%2,%3}, {%4,%5,%6,%7}, {%8,%9}, {%0,%1,%2,%3};"
        : "+f"(d0), "+f"(d1), "+f"(d2), "+f"(d3)
        : "r"(a0), "r"(a1), "r"(a2), "r"(a3), "r"(b0), "r"(b1));
}
__device__ __forceinline__ void mma16h(float& d0, float& d1, float& d2, float& d3,
                                       uint32_t a0, uint32_t a1, uint32_t a2, uint32_t a3,
                                       uint32_t b0, uint32_t b1) {
    asm volatile(
        "mma.sync.aligned.m16n8k16.row.col.f32.f16.f16.f32 "
        "{%0,%1,%2,%3}, {%4,%5,%6,%7}, {%8,%9}, {%0,%1,%2,%3};"
        : "+f"(d0), "+f"(d1), "+f"(d2), "+f"(d3)
        : "r"(a0), "r"(a1), "r"(a2), "r"(a3), "r"(b0), "r"(b1));
}
// gate interleave: output col j <- original weight row (j&3)*128 + (j>>2)
__device__ __forceinline__ int gperm(int j) { return (j & 3) * 128 + (j >> 2); }

// ---------------- prep: token lengths + backward-input row map ----------------
__global__ void prep_tok(const int* __restrict__ units, int* __restrict__ toklen,
                         int* __restrict__ rm_b) {
    int n = blockIdx.x * blockDim.x + threadIdx.x;
    if (n >= NU) return;
    int len = T_TOK;
    for (int t = 0; t < T_TOK; t++)
        if (units[t*NU + n] == 0) { len = t; break; }
    toklen[n] = len;
    for (int s = 0; s < T_TOK; s++) {
        int st = len - 1 - s;
        st = st < 0 ? 0 : (st > T_TOK-1 ? T_TOK-1 : st);
        rm_b[s*NU + n] = units[st*NU + n];
    }
}

// ---------------- prep: path lengths + gather row maps ----------------
__global__ void prep_path(const int* __restrict__ paths, const int* __restrict__ upd,
                          const int* __restrict__ ppd, int* __restrict__ plen_out,
                          int* __restrict__ rm_f, int* __restrict__ rm_b) {
    int p = blockIdx.x * blockDim.x + threadIdx.x;
    if (p >= NP) return;
    int d = 0, cum = 0;
    for (int i = 0; i < 8; i++) { int c = ppd[i]; if (p < cum + c) { d = i; break; } cum += c; }
    int off = 0;
    for (int i = 0; i < d; i++) off += upd[i];
    int un = upd[d];
    int fe = LP;
    for (int l = 0; l < LP; l++)
        if (paths[l*NP + p] == -1) { fe = l; break; }
    int plen = LP;
    for (int l = 0; l < LP; l++) {
        int pv = paths[l*NP + p];
        bool m = (l < fe) ? (pv < 0 || pv > un) : true;
        if (m) { plen = l; break; }
    }
    plen_out[p] = plen;
    for (int l = 0; l < LP; l++) {
        int pv = paths[l*NP + p];
        bool keep = (l < fe) && pv >= 0 && pv < un;
        int pvc = pv < 0 ? 0 : pv;
        int gidx = pvc + off; if (gidx > NU-1) gidx = NU-1;
        rm_f[l*NP + p] = keep ? gidx : -1;
    }
    for (int s = 0; s < LP; s++) {
        int sl = plen - 1 - s;
        sl = sl < 0 ? 0 : (sl > LP-1 ? LP-1 : sl);
        int pv = paths[sl*NP + p];
        bool keep = (sl < fe) && pv >= 0 && pv < un;
        int pvc = pv < 0 ? 0 : pv;
        int gidx = pvc + off; if (gidx > NU-1) gidx = NU-1;
        rm_b[s*NP + p] = keep ? gidx : -1;
    }
}

// ===================== tf32 mma.sync GEMM (unchanged) =====================
__global__ __launch_bounds__(256) void mma_gemm(
    const float* __restrict__ A, const int* __restrict__ rowmap,
    const float* __restrict__ B, const float* __restrict__ bias,
    void* __restrict__ Cv, int M, int N, int K, int permB, int outHalf)
{
    __shared__ uint32_t As[128][36];
    __shared__ uint32_t Bs[128][36];
    __shared__ int rid[128];
    int tid = threadIdx.x, lane = tid & 31, wid = tid >> 5;
    int wm = (wid >> 2) * 64, wn = (wid & 3) * 32;
    int m0 = blockIdx.y * 128, n0 = blockIdx.x * 128;
    if (tid < 128) rid[tid] = rowmap ? rowmap[m0 + tid] : (m0 + tid);
    float acc[4][4][4];
#pragma unroll
    for (int a = 0; a < 4; a++)
#pragma unroll
        for (int b = 0; b < 4; b++)
#pragma unroll
            for (int q = 0; q < 4; q++) acc[a][b][q] = 0.f;
    __syncthreads();

    for (int kc = 0; kc < K; kc += 32) {
        for (int i = tid; i < 1024; i += 256) {
            int r = i >> 3, q = i & 7;
            int src = rid[r];
            float4 v = make_float4(0.f, 0.f, 0.f, 0.f);
            if (src >= 0) v = *(const float4*)(A + (size_t)src * K + kc + q * 4);
            As[r][q*4+0] = f2tf(v.x); As[r][q*4+1] = f2tf(v.y);
            As[r][q*4+2] = f2tf(v.z); As[r][q*4+3] = f2tf(v.w);
        }
        for (int i = tid; i < 1024; i += 256) {
            int r = i >> 3, q = i & 7;
            int srcr = permB ? gperm(n0 + r) : (n0 + r);
            float4 v = *(const float4*)(B + (size_t)srcr * K + kc + q * 4);
            Bs[r][q*4+0] = f2tf(v.x); Bs[r][q*4+1] = f2tf(v.y);
            Bs[r][q*4+2] = f2tf(v.z); Bs[r][q*4+3] = f2tf(v.w);
        }
        __syncthreads();
#pragma unroll
        for (int ks = 0; ks < 4; ks++) {
            int kc4 = ks * 8 + (lane & 3);
            uint32_t af[4][4];
#pragma unroll
            for (int ma = 0; ma < 4; ma++) {
                int r = wm + ma * 16 + (lane >> 2);
                af[ma][0] = As[r    ][kc4];
                af[ma][1] = As[r + 8][kc4];
                af[ma][2] = As[r    ][kc4 + 4];
                af[ma][3] = As[r + 8][kc4 + 4];
            }
#pragma unroll
            for (int nb = 0; nb < 4; nb++) {
                int cn = wn + nb * 8 + (lane >> 2);
                uint32_t b0 = Bs[cn][kc4];
                uint32_t b1 = Bs[cn][kc4 + 4];
#pragma unroll
                for (int ma = 0; ma < 4; ma++)
                    mma8(acc[ma][nb][0], acc[ma][nb][1], acc[ma][nb][2], acc[ma][nb][3],
                         af[ma][0], af[ma][1], af[ma][2], af[ma][3], b0, b1);
            }
        }
        __syncthreads();
    }
#pragma unroll
    for (int ma = 0; ma < 4; ma++) {
        int m = m0 + wm + ma * 16 + (lane >> 2);
#pragma unroll
        for (int nb = 0; nb < 4; nb++) {
            int j = n0 + wn + nb * 8 + (lane & 3) * 2;
            float b0v = bias[permB ? gperm(j)     : j];
            float b1v = bias[permB ? gperm(j + 1) : j + 1];
            if (outHalf) {
                __half* C = (__half*)Cv;
                *(__half2*)(C + (size_t)m * N + j) =
                    __floats2half2_rn(acc[ma][nb][0] + b0v, acc[ma][nb][1] + b1v);
                *(__half2*)(C + (size_t)(m + 8) * N + j) =
                    __floats2half2_rn(acc[ma][nb][2] + b0v, acc[ma][nb][3] + b1v);
            } else {
                float* C = (float*)Cv;
                *(float2*)(C + (size_t)m * N + j) =
                    make_float2(acc[ma][nb][0] + b0v, acc[ma][nb][1] + b1v);
                *(float2*)(C + (size_t)(m + 8) * N + j) =
                    make_float2(acc[ma][nb][2] + b0v, acc[ma][nb][3] + b1v);
            }
        }
    }
}

// ===================== CTA-local BiLSTM recurrence (no grid sync) =====================
// Each CTA owns (dir, MB*16 batch rows) and computes ALL 512 gate columns.
// Wh (gate-interleaved, fp16) resident in SMEM; h double-buffered fp16 in SMEM;
// c fp32 in SMEM. One __syncthreads per step. fp16 mma.sync m16n8k16, fp32 accum.
#define P2_WS   0                         // 512 x 136 half = 139264 B
#define P2_HS   139264                    // 2 x 64 x 136 half = 34816 B
#define P2_CS   174080                    // 64 x 132 f32 = 33792 B
#define P2_SMEM 207872

__global__ __launch_bounds__(256) void lstm_persist2(
    const __half* __restrict__ gpre_f, const __half* __restrict__ gpre_b,
    float* __restrict__ hf_, float* __restrict__ hb_,
    const float* __restrict__ Whf, const float* __restrict__ Whb,
    int batch, int T, int MB)          // MB = #16-row m-blocks per CTA
{
    extern __shared__ char smch[];
    __half* Ws = (__half*)(smch + P2_WS);      // [512][136]
    __half* Hs = (__half*)(smch + P2_HS);      // [2][64][136]
    float*  Cs = (float*)(smch + P2_CS);       // [64][132]

    int dir = blockIdx.y;
    int m0  = blockIdx.x * MB * 16;
    const __half* gpre = dir ? gpre_b : gpre_f;
    float*        hout = dir ? hb_    : hf_;
    const float*  Wh   = dir ? Whb    : Whf;

    int tid = threadIdx.x, lane = tid & 31, wid = tid >> 5;
    int gq4 = lane >> 2, q = lane & 3;

    // load Wh (gate-interleaved rows) once, f32 -> fp16
    for (int i = tid; i < 512 * 64; i += 256) {
        int n = i >> 6, kk = (i & 63) * 2;
        float2 v = *(const float2*)(Wh + (size_t)gperm(n) * 128 + kk);
        *(__half2*)(Ws + n * 136 + kk) = __floats2half2_rn(v.x, v.y);
    }
    for (int i = tid; i < 64 * 132; i += 256) Cs[i] = 0.f;
    __syncthreads();

    for (int t = 0; t < T; t++) {
        const __half* gp = gpre + (size_t)t * batch * 512;
        float* hrow = hout + (size_t)t * batch * 128;
        __half* hw = Hs + (size_t)(t & 1) * 64 * 136;          // write h[t]
        const __half* hr = Hs + (size_t)((t & 1) ^ 1) * 64 * 136;  // read h[t-1]

        for (int mb = 0; mb < MB; mb++) {
            // prefetch gpre for this m-block (MLP=16 hides latency behind mma)
            uint32_t gqv[8][2];
#pragma unroll
            for (int nf = 0; nf < 8; nf++) {
                int jg = wid * 64 + nf * 8 + q * 2;
#pragma unroll
                for (int hh = 0; hh < 2; hh++) {
                    int mh = m0 + mb * 16 + gq4 + hh * 8;
                    gqv[nf][hh] = *(const uint32_t*)(gp + (size_t)mh * 512 + jg);
                }
            }
            // A fragments for this m-block (reused across 8 n-frags)
            uint32_t af[8][4];
            if (t > 0) {
#pragma unroll
                for (int kc = 0; kc < 8; kc++) {
                    int r = mb * 16 + gq4;
                    int k = kc * 16 + q * 2;
                    af[kc][0] = *(const uint32_t*)(hr + (r    ) * 136 + k);
                    af[kc][1] = *(const uint32_t*)(hr + (r + 8) * 136 + k);
                    af[kc][2] = *(const uint32_t*)(hr + (r    ) * 136 + k + 8);
                    af[kc][3] = *(const uint32_t*)(hr + (r + 8) * 136 + k + 8);
                }
            }
#pragma unroll
            for (int nf = 0; nf < 8; nf++) {
                float d0 = 0.f, d1 = 0.f, d2 = 0.f, d3 = 0.f;
                if (t > 0) {
                    int n = wid * 64 + nf * 8 + gq4;
#pragma unroll
                    for (int kc = 0; kc < 8; kc++) {
                        int k = kc * 16 + q * 2;
                        uint32_t b0 = *(const uint32_t*)(Ws + n * 136 + k);
                        uint32_t b1 = *(const uint32_t*)(Ws + n * 136 + k + 8);
                        mma16h(d0, d1, d2, d3,
                               af[kc][0], af[kc][1], af[kc][2], af[kc][3], b0, b1);
                    }
                }
                int jg = wid * 64 + nf * 8 + q * 2;
#pragma unroll
                for (int hh = 0; hh < 2; hh++) {
                    int mloc = mb * 16 + gq4 + hh * 8;
                    float2 gf2 = __half22float2(*(__half2*)&gqv[nf][hh]);
                    float g0 = (hh ? d2 : d0) + gf2.x;
                    float g1 = (hh ? d3 : d1) + gf2.y;
                    float p0 = __shfl_xor_sync(0xffffffffu, g0, 1);
                    float p1 = __shfl_xor_sync(0xffffffffu, g1, 1);
                    if (!(lane & 1)) {
                        int cl = jg >> 2;
                        float cold = Cs[mloc * 132 + cl];
                        float cn = sigm(g1) * cold + sigm(g0) * tanhf(p0);
                        float hn = sigm(p1) * tanhf(cn);
                        Cs[mloc * 132 + cl] = cn;
                        hw[mloc * 136 + cl] = __float2half(hn);
                        hrow[(size_t)(m0 + mloc) * 128 + cl] = hn;
                    }
                }
            }
        }
        __syncthreads();   // h[t] fully in SMEM before step t+1 reads it
    }
}

// ---------------- concat fwd/bwd hidden states ----------------
__global__ void hcat_tok(const float* __restrict__ hf, const float* __restrict__ hb,
                         const int* __restrict__ toklen, float* __restrict__ hcat) {
    size_t idx = (size_t)blockIdx.x * 256 + threadIdx.x;
    int k = (int)(idx & 127);
    size_t row = idx >> 7;
    int n = (int)(row & (NU-1));
    int t = (int)(row >> 12);
    int len = toklen[n];
    bool valid = t < len;
    int rev = len - 1 - t;
    rev = rev < 0 ? 0 : (rev > T_TOK-1 ? T_TOK-1 : rev);
    float vf = valid ? hf[idx] : 0.f;
    float vb = valid ? hb[((size_t)(rev*NU + n))*128 + k] : 0.f;
    hcat[row*256 + k]       = vf;
    hcat[row*256 + 128 + k] = vb;
}

__global__ void hcat_path(const float* __restrict__ hpf, const float* __restrict__ hpb,
                          const int* __restrict__ plen, float* __restrict__ hcatp) {
    size_t idx = (size_t)blockIdx.x * 256 + threadIdx.x;
    int k = (int)(idx & 127);
    size_t row = idx >> 7;
    int p = (int)(row & (NP-1));
    int l = (int)(row >> 10);
    int pl = plen[p];
    bool valid = l < pl;
    int rev = pl - 1 - l;
    rev = rev < 0 ? 0 : (rev > LP-1 ? LP-1 : rev);
    float vf = valid ? hpf[idx] : 0.f;
    float vb = valid ? hpb[((size_t)(rev*NP + p))*128 + k] : 0.f;
    hcatp[row*256 + k]       = vf;
    hcatp[row*256 + 128 + k] = vb;
}

// ---------------- attention ----------------
__device__ __forceinline__ float blk_sum128(float v, float* r4) {
#pragma unroll
    for (int o = 16; o > 0; o >>= 1) v += __shfl_xor_sync(0xffffffffu, v, o);
    __syncthreads();
    if ((threadIdx.x & 31) == 0) r4[threadIdx.x >> 5] = v;
    __syncthreads();
    return r4[0] + r4[1] + r4[2] + r4[3];
}

__global__ void attn_kernel(const float* __restrict__ outlin, const int* __restrict__ toklen,
                            const float* __restrict__ ln_g, const float* __restrict__ ln_b,
                            const float* __restrict__ attn_w, const float* __restrict__ attn_b,
                            float* __restrict__ tokfeat) {
    int n = blockIdx.x, e = threadIdx.x;
    __shared__ float r4[4];
    __shared__ float sc[T_TOK];
    int len = toklen[n];
    float g = ln_g[e], bb = ln_b[e], aw = attn_w[e], ab = attn_b[0];
    float xv[T_TOK];
    for (int t = 0; t < T_TOK; t++) {
        float x = outlin[((size_t)(t*NU + n))*128 + e];
        xv[t] = x;
        float m = blk_sum128(x, r4) * (1.f/128.f);
        float d = x - m;
        float v = blk_sum128(d*d, r4) * (1.f/128.f);
        float q = tanhf(d * rsqrtf(v + 1e-5f) * g + bb);
        float s = blk_sum128(q * aw, r4);
        if (e == 0) sc[t] = (t < len) ? (s + ab) : -1e9f;
    }
    __syncthreads();
    float mx = -3.4e38f;
#pragma unroll
    for (int t = 0; t < T_TOK; t++) mx = fmaxf(mx, sc[t]);
    float ww[T_TOK]; float den = 0.f;
#pragma unroll
    for (int t = 0; t < T_TOK; t++) { ww[t] = expf(sc[t] - mx); den += ww[t]; }
    float inv = 1.f / den;
    float acc = 0.f;
#pragma unroll
    for (int t = 0; t < T_TOK; t++) acc += ww[t] * inv * xv[t];
    tokfeat[(size_t)n*128 + e] = acc;
}

// ---------------- host ----------------
extern "C" void kernel_launch(void* const* d_in, const int* in_sizes, int n_in,
                              void* d_out, int out_size) {
    const int*   units   = (const int*)d_in[0];
    const int*   paths   = (const int*)d_in[1];
    const int*   upd     = (const int*)d_in[2];
    const int*   ppd     = (const int*)d_in[3];
    const float* emb     = (const float*)d_in[4];
    const float* tl_Wif  = (const float*)d_in[5];
    const float* tl_Whf  = (const float*)d_in[6];
    const float* tl_bf   = (const float*)d_in[7];
    const float* tl_Wib  = (const float*)d_in[8];
    const float* tl_Whb  = (const float*)d_in[9];
    const float* tl_bb   = (const float*)d_in[10];
    const float* lin_W   = (const float*)d_in[11];
    const float* lin_b   = (const float*)d_in[12];
    const float* ln_g    = (const float*)d_in[13];
    const float* ln_bb   = (const float*)d_in[14];
    const float* attn_w  = (const float*)d_in[15];
    const float* attn_b  = (const float*)d_in[16];
    const float* pl_Wif  = (const float*)d_in[17];
    const float* pl_Whf  = (const float*)d_in[18];
    const float* pl_bf   = (const float*)d_in[19];
    const float* pl_Wib  = (const float*)d_in[20];
    const float* pl_Whb  = (const float*)d_in[21];
    const float* pl_bb   = (const float*)d_in[22];
    const float* ul_W    = (const float*)d_in[23];
    const float* ul_b    = (const float*)d_in[24];
    float* out = (float*)d_out;

    __half *gpre_f, *gpre_b, *gpre_pf, *gpre_pb;
    float *hf, *hb, *hcat, *outlin, *tokfeat, *hpf, *hpb, *hcatp;
    int *toklen, *rm_tb, *rm_pf, *rm_pb, *plen;
    cudaGetSymbolAddress((void**)&gpre_f,  g_gpre_f);
    cudaGetSymbolAddress((void**)&gpre_b,  g_gpre_b);
    cudaGetSymbolAddress((void**)&hf,      g_hf);
    cudaGetSymbolAddress((void**)&hb,      g_hb);
    cudaGetSymbolAddress((void**)&hcat,    g_hcat);
    cudaGetSymbolAddress((void**)&outlin,  g_outlin);
    cudaGetSymbolAddress((void**)&tokfeat, g_tokfeat);
    cudaGetSymbolAddress((void**)&gpre_pf, g_gpre_pf);
    cudaGetSymbolAddress((void**)&gpre_pb, g_gpre_pb);
    cudaGetSymbolAddress((void**)&hpf,     g_hpf);
    cudaGetSymbolAddress((void**)&hpb,     g_hpb);
    cudaGetSymbolAddress((void**)&hcatp,   g_hcatp);
    cudaGetSymbolAddress((void**)&toklen,  g_toklen);
    cudaGetSymbolAddress((void**)&rm_tb,   g_rm_tb);
    cudaGetSymbolAddress((void**)&rm_pf,   g_rm_pf);
    cudaGetSymbolAddress((void**)&rm_pb,   g_rm_pb);
    cudaGetSymbolAddress((void**)&plen,    g_plen);

    cudaFuncSetAttribute(lstm_persist2, cudaFuncAttributeMaxDynamicSharedMemorySize,
                         P2_SMEM);

    prep_tok<<<(NU+255)/256, 256>>>(units, toklen, rm_tb);

    // token input-gate GEMMs (tf32 mma, gate-interleaved fp16 output)
    mma_gemm<<<dim3(4, T_TOK*NU/128), 256>>>(emb, units, tl_Wif, tl_bf, gpre_f, T_TOK*NU, G4, E, 1, 1);
    mma_gemm<<<dim3(4, T_TOK*NU/128), 256>>>(emb, rm_tb, tl_Wib, tl_bb, gpre_b, T_TOK*NU, G4, E, 1, 1);

    // token recurrence: CTA-local, 64-row slices, no grid sync
    lstm_persist2<<<dim3(NU/64, 2), 256, P2_SMEM>>>(
        gpre_f, gpre_b, hf, hb, tl_Whf, tl_Whb, NU, T_TOK, 4);

    hcat_tok<<<(int)((size_t)T_TOK*NU*H/256), 256>>>(hf, hb, toklen, hcat);
    mma_gemm<<<dim3(1, T_TOK*NU/128), 256>>>(hcat, nullptr, lin_W, lin_b, outlin, T_TOK*NU, E, 2*H, 0, 0);
    attn_kernel<<<NU, 128>>>(outlin, toklen, ln_g, ln_bb, attn_w, attn_b, tokfeat);

    // path side
    prep_path<<<(NP+255)/256, 256>>>(paths, upd, ppd, plen, rm_pf, rm_pb);
    mma_gemm<<<dim3(4, LP*NP/128), 256>>>(tokfeat, rm_pf, pl_Wif, pl_bf, gpre_pf, LP*NP, G4, E, 1, 1);
    mma_gemm<<<dim3(4, LP*NP/128), 256>>>(tokfeat, rm_pb, pl_Wib, pl_bb, gpre_pb, LP*NP, G4, E, 1, 1);

    // path recurrence: 32-row slices
    lstm_persist2<<<dim3(NP/32, 2), 256, P2_SMEM>>>(
        gpre_pf, gpre_pb, hpf, hpb, pl_Whf, pl_Whb, NP, LP, 2);

    hcat_path<<<(int)((size_t)LP*NP*H/256), 256>>>(hpf, hpb, plen, hcatp);
    mma_gemm<<<dim3(1, LP*NP/128), 256>>>(hcatp, nullptr, ul_W, ul_b, out, LP*NP, E, 2*H, 0, 0);
}